// round 13
// baseline (speedup 1.0000x reference)
#include <cuda_runtime.h>
#include <cuda_bf16.h>
#include <cstdint>

#define B_ 8
#define N_ 1024
#define C_ 64

// ---------------- device scratch (allocation-free rule) ----------------
__device__ __nv_bfloat16 g_LH[B_ * N_ * N_];
__device__ __nv_bfloat16 g_LL[B_ * N_ * N_];
__device__ __nv_bfloat16 g_xH[B_ * N_ * C_];
__device__ __nv_bfloat16 g_xL[B_ * N_ * C_];
__device__ __nv_bfloat16 g_z1H[B_ * N_ * C_];
__device__ __nv_bfloat16 g_z1L[B_ * N_ * C_];
__device__ __nv_bfloat16 g_z2H[B_ * N_ * C_];
__device__ __nv_bfloat16 g_z2L[B_ * N_ * C_];
__device__ __nv_bfloat16 g_thH[4 * 64 * 64];   // theta[k][ci][co] bf16-hi
__device__ __nv_bfloat16 g_thL[4 * 64 * 64];   // bf16-lo

// ---------------- helpers ----------------
__device__ __forceinline__ uint32_t smem_u32(const void* p) {
    uint32_t a;
    asm("{ .reg .u64 t; cvta.to.shared.u64 t, %1; cvt.u32.u64 %0, t; }" : "=r"(a) : "l"(p));
    return a;
}
__device__ __forceinline__ void cp16(uint32_t d, const void* s) {
    asm volatile("cp.async.cg.shared.global [%0], [%1], 16;" :: "r"(d), "l"(s));
}
#define CP_COMMIT() asm volatile("cp.async.commit_group;" ::: "memory")

__device__ __forceinline__ void split2(float a, float b, uint32_t& hi, uint32_t& lo) {
    __nv_bfloat16 ha = __float2bfloat16(a), hb = __float2bfloat16(b);
    hi = (uint32_t)__bfloat16_as_ushort(ha) | ((uint32_t)__bfloat16_as_ushort(hb) << 16);
    __nv_bfloat16 la = __float2bfloat16(a - __bfloat162float(ha));
    __nv_bfloat16 lb = __float2bfloat16(b - __bfloat162float(hb));
    lo = (uint32_t)__bfloat16_as_ushort(la) | ((uint32_t)__bfloat16_as_ushort(lb) << 16);
}
__device__ __forceinline__ float recon(uint32_t h, uint32_t l, int idx) {
    unsigned short hs = (unsigned short)(idx ? (h >> 16) : (h & 0xFFFF));
    unsigned short ls = (unsigned short)(idx ? (l >> 16) : (l & 0xFFFF));
    return __bfloat162float(__ushort_as_bfloat16(hs)) + __bfloat162float(__ushort_as_bfloat16(ls));
}

#define LDSM4(R, A) asm volatile( \
    "ldmatrix.sync.aligned.m8n8.x4.shared.b16 {%0,%1,%2,%3}, [%4];" \
    : "=r"((R)[0]), "=r"((R)[1]), "=r"((R)[2]), "=r"((R)[3]) : "r"(A))
#define LDSM4T(R, A) asm volatile( \
    "ldmatrix.sync.aligned.m8n8.x4.trans.shared.b16 {%0,%1,%2,%3}, [%4];" \
    : "=r"((R)[0]), "=r"((R)[1]), "=r"((R)[2]), "=r"((R)[3]) : "r"(A))
#define MMA16816(D, A, B0, B1) asm volatile( \
    "mma.sync.aligned.m16n8k16.row.col.f32.bf16.bf16.f32 " \
    "{%0,%1,%2,%3},{%4,%5,%6,%7},{%8,%9},{%0,%1,%2,%3};" \
    : "+f"((D)[0]), "+f"((D)[1]), "+f"((D)[2]), "+f"((D)[3]) \
    : "r"((A)[0]), "r"((A)[1]), "r"((A)[2]), "r"((A)[3]), "r"(B0), "r"(B1))

// 16m x 32n per warp, K=64 chunk, bf16-split (HH + HL + LH). R4-proven.
__device__ __forceinline__ void mma_block64(
    uint32_t aH, uint32_t aL, uint32_t bH, uint32_t bL,
    int wm, int wn, int lane, float acc[4][4]) {
    const int tile = lane >> 3, tl = lane & 7;
    const int arow = wm * 16 + ((tile & 1) << 3) + tl;
    const uint32_t arb = (uint32_t)arow * 128;
    const int arx = arow & 7;
    const int aks0 = tile >> 1;
    const int krl = ((tile & 1) << 3) + tl;
    const int bs0 = wn * 4 + (tile >> 1);
    #pragma unroll
    for (int kk = 0; kk < 4; kk++) {
        uint32_t aso = arb + (uint32_t)(((aks0 + kk * 2) ^ arx) << 4);
        uint32_t AH4[4], AL4[4];
        LDSM4(AH4, aH + aso);
        LDSM4(AL4, aL + aso);
        const int kr = kk * 16 + krl;
        const int krx = kr & 7;
        const uint32_t krb = (uint32_t)kr * 128;
        uint32_t bso0 = krb + (uint32_t)(((bs0 + 0) ^ krx) << 4);
        uint32_t bso1 = krb + (uint32_t)(((bs0 + 2) ^ krx) << 4);
        uint32_t BH0[4], BH1[4], BL0[4], BL1[4];
        LDSM4T(BH0, bH + bso0);
        LDSM4T(BH1, bH + bso1);
        LDSM4T(BL0, bL + bso0);
        LDSM4T(BL1, bL + bso1);
        MMA16816(acc[0], AH4, BH0[0], BH0[1]);
        MMA16816(acc[1], AH4, BH0[2], BH0[3]);
        MMA16816(acc[2], AH4, BH1[0], BH1[1]);
        MMA16816(acc[3], AH4, BH1[2], BH1[3]);
        MMA16816(acc[0], AH4, BL0[0], BL0[1]);
        MMA16816(acc[1], AH4, BL0[2], BL0[3]);
        MMA16816(acc[2], AH4, BL1[0], BL1[1]);
        MMA16816(acc[3], AH4, BL1[2], BL1[3]);
        MMA16816(acc[0], AL4, BH0[0], BH0[1]);
        MMA16816(acc[1], AL4, BH0[2], BH0[3]);
        MMA16816(acc[2], AL4, BH1[0], BH1[1]);
        MMA16816(acc[3], AL4, BH1[2], BH1[3]);
    }
}

// ---------------- prep: fp32 -> bf16 hi/lo split (x, theta only) ----------------
__global__ __launch_bounds__(256) void split_k(const float4* __restrict__ s,
                                               uint2* __restrict__ h,
                                               uint2* __restrict__ l, int n4) {
    for (int i = blockIdx.x * blockDim.x + threadIdx.x; i < n4; i += gridDim.x * blockDim.x) {
        float4 v = s[i];
        uint32_t h0, l0, h1, l1;
        split2(v.x, v.y, h0, l0);
        split2(v.z, v.w, h1, l1);
        h[i] = make_uint2(h0, h1);
        l[i] = make_uint2(l0, l1);
    }
}

// ---------------- main pass kernel ----------------
// M-tile = 64 rows, 256 threads (8 warps: wm{0..3} x wn{0,1}), full K per warp.
// PASS 1: 2 stages of 48KB: AF32 [0,16K) AH [16K,24K) AL [24K,32K) BH [32K,40K) BL [40K,48K)
//         (fused fp32->hi/lo split; hi/lo persisted to g_LH/g_LL for passes 2/3)
// PASS 2/3: 3 stages of 32KB (R4): AH [0,8K) AL [8K,16K) BH [16K,24K) BL [24K,32K)
// Epilogue region at +98304 for both.
#define STG1   49152
#define STG23  32768
#define O_E    98304
#define O_ZH   (O_E + 0)
#define O_ZL   (O_E + 8192)
#define O_TH   (O_E + 16384)
#define O_TL   (O_E + 24576)
#define O_XH   (O_E + 32768)
#define O_XL   (O_E + 40960)
#define O_T0H  (O_E + 49152)
#define O_T0L  (O_E + 57344)
#define SMEMSZ1  (O_E + 65536)   // 163840
#define SMEMSZ23 (O_E + 32768)   // 131072

template <int PASS>
__global__ void __launch_bounds__(256, 1) cheb(
    const float* __restrict__ Lf,                                        // PASS 1
    const __nv_bfloat16* __restrict__ LH, const __nv_bfloat16* __restrict__ LL,  // PASS 2/3
    const __nv_bfloat16* __restrict__ BHg, const __nv_bfloat16* __restrict__ BLg,
    const __nv_bfloat16* __restrict__ SubH, const __nv_bfloat16* __restrict__ SubL,
    const __nv_bfloat16* __restrict__ thH, const __nv_bfloat16* __restrict__ thL,
    const __nv_bfloat16* __restrict__ xH, const __nv_bfloat16* __restrict__ xL,
    __nv_bfloat16* __restrict__ ZoH, __nv_bfloat16* __restrict__ ZoL,
    __nv_bfloat16* __restrict__ LHo, __nv_bfloat16* __restrict__ LLo,    // PASS 1
    float* __restrict__ out) {

    extern __shared__ char smem[];
    const uint32_t sb = smem_u32(smem);
    const int tid = threadIdx.x, lane = tid & 31, wid = tid >> 5;
    const int wm = wid & 3, wn = wid >> 2;
    const int b = blockIdx.y, m0 = blockIdx.x * 64;

    const __nv_bfloat16* BpH = BHg + (size_t)b * N_ * C_;
    const __nv_bfloat16* BpL = BLg + (size_t)b * N_ * C_;

    auto load_chunk = [&](int k0, int s) {
        if (PASS == 1) {
            const uint32_t st = sb + (uint32_t)s * STG1;
            // fp32 A: 64 rows x 64 floats = 16KB -> 1024 cp16, 4/thread
            #pragma unroll
            for (int i = 0; i < 4; i++) {
                const int idx = tid + i * 256;
                const int row = idx >> 4, sg = idx & 15;
                cp16(st + (uint32_t)row * 256 + sg * 16,
                     Lf + ((size_t)(b * N_ + m0 + row)) * N_ + k0 + sg * 4);
            }
            // B hi/lo: 2/thread each half
            #pragma unroll
            for (int i = 0; i < 2; i++) {
                const int idx = tid + i * 256;
                const int row = idx >> 3, seg = idx & 7;
                const uint32_t so = (uint32_t)row * 128 + (uint32_t)((seg ^ (row & 7)) << 4);
                cp16(st + 32768 + so, BpH + (size_t)(k0 + row) * C_ + seg * 8);
                cp16(st + 40960 + so, BpL + (size_t)(k0 + row) * C_ + seg * 8);
            }
        } else {
            const uint32_t st = sb + (uint32_t)s * STG23;
            const __nv_bfloat16* ApH = LH + ((size_t)(b * N_ + m0)) * N_;
            const __nv_bfloat16* ApL = LL + ((size_t)(b * N_ + m0)) * N_;
            #pragma unroll
            for (int i = 0; i < 2; i++) {
                const int idx = tid + i * 256;
                const int row = idx >> 3, seg = idx & 7;
                const uint32_t so = (uint32_t)row * 128 + (uint32_t)((seg ^ (row & 7)) << 4);
                cp16(st + so,         ApH + (size_t)row * N_ + k0 + seg * 8);
                cp16(st + 8192 + so,  ApL + (size_t)row * N_ + k0 + seg * 8);
                cp16(st + 16384 + so, BpH + (size_t)(k0 + row) * C_ + seg * 8);
                cp16(st + 24576 + so, BpL + (size_t)(k0 + row) * C_ + seg * 8);
            }
        }
        CP_COMMIT();
    };

    float acc[4][4] = {};

    if (PASS == 1) {
        load_chunk(0, 0);
        load_chunk(64, 1);
        for (int ch = 0; ch < 16; ch++) {
            if (ch < 15) asm volatile("cp.async.wait_group 1;" ::: "memory");
            else         asm volatile("cp.async.wait_group 0;" ::: "memory");
            __syncthreads();
            const int s = ch & 1;
            const uint32_t st = sb + (uint32_t)s * STG1;
            char* stp = smem + (size_t)s * STG1;

            // fp32 -> bf16 hi/lo (separate smem regions; no in-place hazard)
            {
                const int r = tid >> 2, q = tid & 3;   // 64 rows x 4 quarters
                float4 f[4];
                #pragma unroll
                for (int j = 0; j < 4; j++)
                    f[j] = *(const float4*)(stp + r * 256 + q * 64 + j * 16);
                uint32_t h[8], l[8];
                #pragma unroll
                for (int j = 0; j < 4; j++) {
                    split2(f[j].x, f[j].y, h[2 * j], l[2 * j]);
                    split2(f[j].z, f[j].w, h[2 * j + 1], l[2 * j + 1]);
                }
                #pragma unroll
                for (int p = 0; p < 2; p++) {
                    const int seg = q * 2 + p;
                    const uint32_t so = (uint32_t)r * 128 + (uint32_t)((seg ^ (r & 7)) << 4);
                    uint4 hv = make_uint4(h[4 * p], h[4 * p + 1], h[4 * p + 2], h[4 * p + 3]);
                    uint4 lv = make_uint4(l[4 * p], l[4 * p + 1], l[4 * p + 2], l[4 * p + 3]);
                    *(uint4*)(stp + 16384 + so) = hv;
                    *(uint4*)(stp + 24576 + so) = lv;
                    const size_t go = ((size_t)(b * N_ + m0 + r)) * N_ + ch * 64 + seg * 8;
                    *(uint4*)(LHo + go) = hv;
                    *(uint4*)(LLo + go) = lv;
                }
            }
            __syncthreads();
            mma_block64(st + 16384, st + 24576, st + 32768, st + 40960, wm, wn, lane, acc);
            __syncthreads();   // stage reads done before reload
            if (ch + 2 < 16) load_chunk((ch + 2) * 64, (ch + 2) & 1);
        }
    } else {
        load_chunk(0, 0);
        load_chunk(64, 1);
        for (int ch = 0; ch < 16; ch++) {
            if (ch < 15) asm volatile("cp.async.wait_group 1;" ::: "memory");
            else         asm volatile("cp.async.wait_group 0;" ::: "memory");
            __syncthreads();
            const uint32_t st = sb + (uint32_t)(ch % 3) * STG23;
            mma_block64(st, st + 8192, st + 16384, st + 24576, wm, wn, lane, acc);
            if (ch + 2 < 16) load_chunk((ch + 2) * 64, (ch + 2) % 3);
        }
    }

    // ---- zn = alpha*acc - Sub (Sub reconstructed from bf16 hi+lo) ----
    const int crow = wm * 16 + (lane >> 2);
    const int ccol = wn * 32 + 2 * (lane & 3);
    float zn[4][4];
    if (PASS == 1) {
        #pragma unroll
        for (int j = 0; j < 4; j++)
            #pragma unroll
            for (int q = 0; q < 4; q++) zn[j][q] = acc[j][q];
    } else {
        #pragma unroll
        for (int j = 0; j < 4; j++) {
            #pragma unroll
            for (int h2 = 0; h2 < 2; h2++) {
                const size_t off = ((size_t)(b * N_ + m0 + crow + 8 * h2)) * C_ + ccol + j * 8;
                uint32_t sh = *(const uint32_t*)(SubH + off);
                uint32_t sl = *(const uint32_t*)(SubL + off);
                zn[j][2 * h2]     = 2.f * acc[j][2 * h2]     - recon(sh, sl, 0);
                zn[j][2 * h2 + 1] = 2.f * acc[j][2 * h2 + 1] - recon(sh, sl, 1);
            }
        }
    }

    // zn -> smem (bf16 hi/lo, SW128 rows)
    #pragma unroll
    for (int j = 0; j < 4; j++) {
        const int seg = wn * 4 + j;
        const int off = (lane & 3) * 4;
        #pragma unroll
        for (int h2 = 0; h2 < 2; h2++) {
            const int row = crow + h2 * 8;
            uint32_t hi, lo;
            split2(zn[j][2 * h2], zn[j][2 * h2 + 1], hi, lo);
            const uint32_t so = (uint32_t)row * 128 + (uint32_t)((seg ^ (row & 7)) << 4) + off;
            *(uint32_t*)(smem + O_ZH + so) = hi;
            *(uint32_t*)(smem + O_ZL + so) = lo;
        }
    }

    // stage theta (and x, theta0 for pass 1)
    const __nv_bfloat16* tHk = thH + PASS * 4096;
    const __nv_bfloat16* tLk = thL + PASS * 4096;
    #pragma unroll
    for (int i = 0; i < 2; i++) {
        const int idx = tid + i * 256;
        const int row = idx >> 3, seg = idx & 7;
        const uint32_t so = (uint32_t)row * 128 + (uint32_t)((seg ^ (row & 7)) << 4);
        *(uint4*)(smem + O_TH + so) = *(const uint4*)(tHk + row * 64 + seg * 8);
        *(uint4*)(smem + O_TL + so) = *(const uint4*)(tLk + row * 64 + seg * 8);
        if (PASS == 1) {
            *(uint4*)(smem + O_XH + so) = *(const uint4*)(xH + ((size_t)(b * N_ + m0 + row)) * C_ + seg * 8);
            *(uint4*)(smem + O_XL + so) = *(const uint4*)(xL + ((size_t)(b * N_ + m0 + row)) * C_ + seg * 8);
            *(uint4*)(smem + O_T0H + so) = *(const uint4*)(thH + row * 64 + seg * 8);
            *(uint4*)(smem + O_T0L + so) = *(const uint4*)(thL + row * 64 + seg * 8);
        }
    }
    __syncthreads();

    // zn (hi/lo) -> global row-major [N][C]: next pass's B operand
    if (PASS < 3) {
        #pragma unroll
        for (int i = 0; i < 2; i++) {
            const int idx = tid + i * 256;
            const int row = idx >> 3, seg = idx & 7;
            const uint32_t so = (uint32_t)row * 128 + (uint32_t)((seg ^ (row & 7)) << 4);
            *(uint4*)(ZoH + ((size_t)(b * N_ + m0 + row)) * C_ + seg * 8) = *(const uint4*)(smem + O_ZH + so);
            *(uint4*)(ZoL + ((size_t)(b * N_ + m0 + row)) * C_ + seg * 8) = *(const uint4*)(smem + O_ZL + so);
        }
    }

    // theta epilogue on tensor cores: o = zn@theta[PASS] (+ x@theta0 for PASS 1)
    float o[4][4] = {};
    mma_block64(sb + O_ZH, sb + O_ZL, sb + O_TH, sb + O_TL, wm, wn, lane, o);
    if (PASS == 1)
        mma_block64(sb + O_XH, sb + O_XL, sb + O_T0H, sb + O_T0L, wm, wn, lane, o);

    float* ob = out + ((size_t)(b * N_ + m0)) * C_;
    #pragma unroll
    for (int j = 0; j < 4; j++) {
        float2 v0 = make_float2(o[j][0], o[j][1]);
        float2 v1 = make_float2(o[j][2], o[j][3]);
        float* p0 = ob + (size_t)crow * C_ + ccol + j * 8;
        float* p1 = ob + (size_t)(crow + 8) * C_ + ccol + j * 8;
        if (PASS > 1) {
            float2 c0 = *(const float2*)p0, c1 = *(const float2*)p1;
            v0.x += c0.x; v0.y += c0.y; v1.x += c1.x; v1.y += c1.y;
        }
        *(float2*)p0 = v0;
        *(float2*)p1 = v1;
    }
}

extern "C" void kernel_launch(void* const* d_in, const int* in_sizes, int n_in,
                              void* d_out, int out_size) {
    (void)in_sizes; (void)n_in; (void)out_size;
    const float* x  = (const float*)d_in[0];   // [8,1024,64]
    const float* L  = (const float*)d_in[1];   // [8,1024,1024]
    const float* th = (const float*)d_in[2];   // [4,64,64]
    float* out = (float*)d_out;                // [8,1024,64]

    __nv_bfloat16 *lh, *ll, *xh, *xl, *z1h, *z1l, *z2h, *z2l, *thh, *thl;
    cudaGetSymbolAddress((void**)&lh, g_LH);
    cudaGetSymbolAddress((void**)&ll, g_LL);
    cudaGetSymbolAddress((void**)&xh, g_xH);
    cudaGetSymbolAddress((void**)&xl, g_xL);
    cudaGetSymbolAddress((void**)&z1h, g_z1H);
    cudaGetSymbolAddress((void**)&z1l, g_z1L);
    cudaGetSymbolAddress((void**)&z2h, g_z2H);
    cudaGetSymbolAddress((void**)&z2l, g_z2L);
    cudaGetSymbolAddress((void**)&thh, g_thH);
    cudaGetSymbolAddress((void**)&thl, g_thL);

    static bool attr_done = false;
    if (!attr_done) {
        cudaFuncSetAttribute(cheb<1>, cudaFuncAttributeMaxDynamicSharedMemorySize, SMEMSZ1);
        cudaFuncSetAttribute(cheb<2>, cudaFuncAttributeMaxDynamicSharedMemorySize, SMEMSZ23);
        cudaFuncSetAttribute(cheb<3>, cudaFuncAttributeMaxDynamicSharedMemorySize, SMEMSZ23);
        attr_done = true;
    }

    // small preps: x and theta hi/lo splits (L split fused into pass 1)
    split_k<<<512, 256>>>((const float4*)x, (uint2*)xh, (uint2*)xl, B_ * N_ * C_ / 4);
    split_k<<<16, 256>>>((const float4*)th, (uint2*)thh, (uint2*)thl, 4 * 64 * 64 / 4);

    dim3 grid(16, 8);
    // pass1: z1 = L x ; out  = x@th0 + z1@th1 ; side: z1 hi/lo, LH/LL
    cheb<1><<<grid, 256, SMEMSZ1>>>(L, nullptr, nullptr, xh, xl, nullptr, nullptr,
                                    thh, thl, xh, xl, z1h, z1l, lh, ll, out);
    // pass2: z2 = 2 L z1 - x ; out += z2@th2 ; side: z2 hi/lo
    cheb<2><<<grid, 256, SMEMSZ23>>>(nullptr, lh, ll, z1h, z1l, xh, xl,
                                     thh, thl, xh, xl, z2h, z2l, nullptr, nullptr, out);
    // pass3: z3 = 2 L z2 - z1 ; out += z3@th3
    cheb<3><<<grid, 256, SMEMSZ23>>>(nullptr, lh, ll, z2h, z2l, z1h, z1l,
                                     thh, thl, xh, xl, nullptr, nullptr, nullptr, nullptr, out);
}

// round 14
// speedup vs baseline: 1.0864x; 1.0864x over previous
#include <cuda_runtime.h>
#include <cuda_bf16.h>
#include <cstdint>

#define B_ 8
#define N_ 1024
#define C_ 64

// ---------------- device scratch (allocation-free rule) ----------------
__device__ __nv_bfloat16 g_LH[B_ * N_ * N_];
__device__ __nv_bfloat16 g_LL[B_ * N_ * N_];
__device__ __nv_bfloat16 g_xH[B_ * N_ * C_];
__device__ __nv_bfloat16 g_xL[B_ * N_ * C_];
__device__ __nv_bfloat16 g_z1H[B_ * N_ * C_];
__device__ __nv_bfloat16 g_z1L[B_ * N_ * C_];
__device__ __nv_bfloat16 g_z2H[B_ * N_ * C_];
__device__ __nv_bfloat16 g_z2L[B_ * N_ * C_];
__device__ float         g_Z1f[B_ * N_ * C_];
__device__ __nv_bfloat16 g_thH[4 * 64 * 64];   // theta[k][ci][co] bf16-hi
__device__ __nv_bfloat16 g_thL[4 * 64 * 64];   // bf16-lo

// ---------------- helpers ----------------
__device__ __forceinline__ uint32_t smem_u32(const void* p) {
    uint32_t a;
    asm("{ .reg .u64 t; cvta.to.shared.u64 t, %1; cvt.u32.u64 %0, t; }" : "=r"(a) : "l"(p));
    return a;
}
__device__ __forceinline__ void cp16(uint32_t d, const void* s) {
    asm volatile("cp.async.cg.shared.global [%0], [%1], 16;" :: "r"(d), "l"(s));
}
#define CP_COMMIT() asm volatile("cp.async.commit_group;" ::: "memory")

__device__ __forceinline__ void split2(float a, float b, uint32_t& hi, uint32_t& lo) {
    __nv_bfloat16 ha = __float2bfloat16(a), hb = __float2bfloat16(b);
    hi = (uint32_t)__bfloat16_as_ushort(ha) | ((uint32_t)__bfloat16_as_ushort(hb) << 16);
    __nv_bfloat16 la = __float2bfloat16(a - __bfloat162float(ha));
    __nv_bfloat16 lb = __float2bfloat16(b - __bfloat162float(hb));
    lo = (uint32_t)__bfloat16_as_ushort(la) | ((uint32_t)__bfloat16_as_ushort(lb) << 16);
}

#define LDSM4(R, A) asm volatile( \
    "ldmatrix.sync.aligned.m8n8.x4.shared.b16 {%0,%1,%2,%3}, [%4];" \
    : "=r"((R)[0]), "=r"((R)[1]), "=r"((R)[2]), "=r"((R)[3]) : "r"(A))
#define LDSM4T(R, A) asm volatile( \
    "ldmatrix.sync.aligned.m8n8.x4.trans.shared.b16 {%0,%1,%2,%3}, [%4];" \
    : "=r"((R)[0]), "=r"((R)[1]), "=r"((R)[2]), "=r"((R)[3]) : "r"(A))
#define MMA16816(D, A, B0, B1) asm volatile( \
    "mma.sync.aligned.m16n8k16.row.col.f32.bf16.bf16.f32 " \
    "{%0,%1,%2,%3},{%4,%5,%6,%7},{%8,%9},{%0,%1,%2,%3};" \
    : "+f"((D)[0]), "+f"((D)[1]), "+f"((D)[2]), "+f"((D)[3]) \
    : "r"((A)[0]), "r"((A)[1]), "r"((A)[2]), "r"((A)[3]), "r"(B0), "r"(B1))

// 16m x 32n per warp, K=64 chunk, bf16-split (HH + HL + LH). R4-proven shape.
__device__ __forceinline__ void mma_block64(
    uint32_t aH, uint32_t aL, uint32_t bH, uint32_t bL,
    int wm, int wn, int lane, float acc[4][4]) {
    const int tile = lane >> 3, tl = lane & 7;
    const int arow = wm * 16 + ((tile & 1) << 3) + tl;
    const uint32_t arb = (uint32_t)arow * 128;
    const int arx = arow & 7;
    const int aks0 = tile >> 1;
    const int krl = ((tile & 1) << 3) + tl;
    const int bs0 = wn * 4 + (tile >> 1);
    #pragma unroll
    for (int kk = 0; kk < 4; kk++) {
        uint32_t aso = arb + (uint32_t)(((aks0 + kk * 2) ^ arx) << 4);
        uint32_t AH4[4], AL4[4];
        LDSM4(AH4, aH + aso);
        LDSM4(AL4, aL + aso);
        const int kr = kk * 16 + krl;
        const int krx = kr & 7;
        const uint32_t krb = (uint32_t)kr * 128;
        uint32_t bso0 = krb + (uint32_t)(((bs0 + 0) ^ krx) << 4);
        uint32_t bso1 = krb + (uint32_t)(((bs0 + 2) ^ krx) << 4);
        uint32_t BH0[4], BH1[4], BL0[4], BL1[4];
        LDSM4T(BH0, bH + bso0);
        LDSM4T(BH1, bH + bso1);
        LDSM4T(BL0, bL + bso0);
        LDSM4T(BL1, bL + bso1);
        MMA16816(acc[0], AH4, BH0[0], BH0[1]);
        MMA16816(acc[1], AH4, BH0[2], BH0[3]);
        MMA16816(acc[2], AH4, BH1[0], BH1[1]);
        MMA16816(acc[3], AH4, BH1[2], BH1[3]);
        MMA16816(acc[0], AH4, BL0[0], BL0[1]);
        MMA16816(acc[1], AH4, BL0[2], BL0[3]);
        MMA16816(acc[2], AH4, BL1[0], BL1[1]);
        MMA16816(acc[3], AH4, BL1[2], BL1[3]);
        MMA16816(acc[0], AL4, BH0[0], BH0[1]);
        MMA16816(acc[1], AL4, BH0[2], BH0[3]);
        MMA16816(acc[2], AL4, BH1[0], BH1[1]);
        MMA16816(acc[3], AL4, BH1[2], BH1[3]);
    }
}

// ---------------- prep: fp32 -> bf16 hi/lo split for L, x, theta in ONE launch ----------------
// blocks [0, 2048)      -> L     (2M float4)
// blocks [2048, 2176)   -> x     (128K float4)
// blocks [2176, 2177)   -> theta (4K float4)
__global__ __launch_bounds__(256) void split_all(
    const float4* __restrict__ L4, uint2* __restrict__ lh, uint2* __restrict__ ll,
    const float4* __restrict__ x4, uint2* __restrict__ xh, uint2* __restrict__ xl,
    const float4* __restrict__ t4, uint2* __restrict__ th, uint2* __restrict__ tl) {
    const float4* s;
    uint2 *h, *l;
    int n4, base;
    if (blockIdx.x < 2048) {
        s = L4; h = lh; l = ll; n4 = B_ * N_ * N_ / 4; base = blockIdx.x;
        const int stride = 2048 * 256;
        for (int i = base * 256 + threadIdx.x; i < n4; i += stride) {
            float4 v = s[i];
            uint32_t h0, l0, h1, l1;
            split2(v.x, v.y, h0, l0);
            split2(v.z, v.w, h1, l1);
            h[i] = make_uint2(h0, h1);
            l[i] = make_uint2(l0, l1);
        }
    } else if (blockIdx.x < 2176) {
        s = x4; h = xh; l = xl; n4 = B_ * N_ * C_ / 4; base = blockIdx.x - 2048;
        const int stride = 128 * 256;
        for (int i = base * 256 + threadIdx.x; i < n4; i += stride) {
            float4 v = s[i];
            uint32_t h0, l0, h1, l1;
            split2(v.x, v.y, h0, l0);
            split2(v.z, v.w, h1, l1);
            h[i] = make_uint2(h0, h1);
            l[i] = make_uint2(l0, l1);
        }
    } else {
        s = t4; h = th; l = tl; n4 = 4 * 64 * 64 / 4;
        for (int i = threadIdx.x; i < n4; i += 256) {
            float4 v = s[i];
            uint32_t h0, l0, h1, l1;
            split2(v.x, v.y, h0, l0);
            split2(v.z, v.w, h1, l1);
            h[i] = make_uint2(h0, h1);
            l[i] = make_uint2(l0, l1);
        }
    }
}

// ---------------- main pass kernel (R4 shape, 4-stage, load-first) ----------------
// M-tile = 64 rows, 256 threads (8 warps: wm{0..3} x wn{0,1}), full K per warp.
// stage (32KB): A_hi [0,8K) A_lo [8K,16K) B_hi [16K,24K) B_lo [24K,32K); 4 stages.
// Epilogue aliases stages 0/1 (dead after mainloop).
#define STG    32768
#define O_ZH   0
#define O_ZL   8192
#define O_TH   16384
#define O_TL   24576
#define O_XH   32768
#define O_XL   40960
#define O_T0H  49152
#define O_T0L  57344
#define SMEMSZ (4 * STG)   // 131072

template <int PASS>
__global__ void __launch_bounds__(256, 1) cheb(
    const __nv_bfloat16* __restrict__ LH, const __nv_bfloat16* __restrict__ LL,
    const __nv_bfloat16* __restrict__ BHg, const __nv_bfloat16* __restrict__ BLg,
    const float* __restrict__ Sub,
    const __nv_bfloat16* __restrict__ thH, const __nv_bfloat16* __restrict__ thL,
    const __nv_bfloat16* __restrict__ xH, const __nv_bfloat16* __restrict__ xL,
    float* __restrict__ Zf,
    __nv_bfloat16* __restrict__ ZoH, __nv_bfloat16* __restrict__ ZoL,
    float* __restrict__ out) {

    extern __shared__ char smem[];
    const uint32_t sb = smem_u32(smem);
    const int tid = threadIdx.x, lane = tid & 31, wid = tid >> 5;
    const int wm = wid & 3, wn = wid >> 2;
    const int b = blockIdx.y, m0 = blockIdx.x * 64;

    const __nv_bfloat16* ApH = LH + ((size_t)(b * N_ + m0)) * N_;
    const __nv_bfloat16* ApL = LL + ((size_t)(b * N_ + m0)) * N_;
    const __nv_bfloat16* BpH = BHg + (size_t)b * N_ * C_;
    const __nv_bfloat16* BpL = BLg + (size_t)b * N_ * C_;

    auto load_chunk = [&](int k0, uint32_t st) {
        #pragma unroll
        for (int i = 0; i < 2; i++) {
            const int idx = tid + i * 256;
            const int row = idx >> 3, seg = idx & 7;
            const uint32_t so = (uint32_t)row * 128 + (uint32_t)((seg ^ (row & 7)) << 4);
            cp16(st + so,         ApH + (size_t)row * N_ + k0 + seg * 8);
            cp16(st + 8192 + so,  ApL + (size_t)row * N_ + k0 + seg * 8);
            cp16(st + 16384 + so, BpH + (size_t)(k0 + row) * C_ + seg * 8);
            cp16(st + 24576 + so, BpL + (size_t)(k0 + row) * C_ + seg * 8);
        }
        CP_COMMIT();
    };

    float acc[4][4] = {};
    load_chunk(0, sb);
    load_chunk(64, sb + STG);
    load_chunk(128, sb + 2 * STG);

    for (int ch = 0; ch < 16; ch++) {
        if (ch < 14)       asm volatile("cp.async.wait_group 2;" ::: "memory");
        else if (ch == 14) asm volatile("cp.async.wait_group 1;" ::: "memory");
        else               asm volatile("cp.async.wait_group 0;" ::: "memory");
        __syncthreads();
        const uint32_t st = sb + (uint32_t)(ch & 3) * STG;
        if (ch + 3 < 16)
            load_chunk((ch + 3) * 64, sb + (uint32_t)((ch + 3) & 3) * STG);
        mma_block64(st, st + 8192, st + 16384, st + 24576, wm, wn, lane, acc);
    }
    __syncthreads();   // stage smem dead -> epilogue aliases stages 0/1

    // ---- zn = alpha*acc - Sub ----
    const int crow = wm * 16 + (lane >> 2);
    const int ccol = wn * 32 + 2 * (lane & 3);
    float zn[4][4];
    if (PASS == 1) {
        #pragma unroll
        for (int j = 0; j < 4; j++)
            #pragma unroll
            for (int q = 0; q < 4; q++) zn[j][q] = acc[j][q];
    } else {
        const float* Sb = Sub + ((size_t)(b * N_ + m0)) * C_;
        #pragma unroll
        for (int j = 0; j < 4; j++) {
            float2 s0 = *(const float2*)(Sb + (size_t)crow * C_ + ccol + j * 8);
            float2 s1 = *(const float2*)(Sb + (size_t)(crow + 8) * C_ + ccol + j * 8);
            zn[j][0] = 2.f * acc[j][0] - s0.x;
            zn[j][1] = 2.f * acc[j][1] - s0.y;
            zn[j][2] = 2.f * acc[j][2] - s1.x;
            zn[j][3] = 2.f * acc[j][3] - s1.y;
        }
    }

    // zn -> smem (bf16 hi/lo, SW128 rows)
    #pragma unroll
    for (int j = 0; j < 4; j++) {
        const int seg = wn * 4 + j;
        const int off = (lane & 3) * 4;
        #pragma unroll
        for (int h = 0; h < 2; h++) {
            const int row = crow + h * 8;
            uint32_t hi, lo;
            split2(zn[j][2 * h], zn[j][2 * h + 1], hi, lo);
            const uint32_t so = (uint32_t)row * 128 + (uint32_t)((seg ^ (row & 7)) << 4) + off;
            *(uint32_t*)(smem + O_ZH + so) = hi;
            *(uint32_t*)(smem + O_ZL + so) = lo;
        }
    }
    if (PASS == 1) {  // z1 fp32 for pass3's Sub
        float* Zb = Zf + ((size_t)(b * N_ + m0)) * C_;
        #pragma unroll
        for (int j = 0; j < 4; j++) {
            *(float2*)(Zb + (size_t)crow * C_ + ccol + j * 8)       = make_float2(zn[j][0], zn[j][1]);
            *(float2*)(Zb + (size_t)(crow + 8) * C_ + ccol + j * 8) = make_float2(zn[j][2], zn[j][3]);
        }
    }

    // stage theta (and x, theta0 for pass 1)
    const __nv_bfloat16* tHk = thH + PASS * 4096;
    const __nv_bfloat16* tLk = thL + PASS * 4096;
    #pragma unroll
    for (int i = 0; i < 2; i++) {
        const int idx = tid + i * 256;
        const int row = idx >> 3, seg = idx & 7;
        const uint32_t so = (uint32_t)row * 128 + (uint32_t)((seg ^ (row & 7)) << 4);
        *(uint4*)(smem + O_TH + so) = *(const uint4*)(tHk + row * 64 + seg * 8);
        *(uint4*)(smem + O_TL + so) = *(const uint4*)(tLk + row * 64 + seg * 8);
        if (PASS == 1) {
            *(uint4*)(smem + O_XH + so) = *(const uint4*)(xH + ((size_t)(b * N_ + m0 + row)) * C_ + seg * 8);
            *(uint4*)(smem + O_XL + so) = *(const uint4*)(xL + ((size_t)(b * N_ + m0 + row)) * C_ + seg * 8);
            *(uint4*)(smem + O_T0H + so) = *(const uint4*)(thH + row * 64 + seg * 8);
            *(uint4*)(smem + O_T0L + so) = *(const uint4*)(thL + row * 64 + seg * 8);
        }
    }
    __syncthreads();

    // zn (hi/lo) -> global row-major [N][C]: next pass's B operand
    if (PASS < 3) {
        #pragma unroll
        for (int i = 0; i < 2; i++) {
            const int idx = tid + i * 256;
            const int row = idx >> 3, seg = idx & 7;
            const uint32_t so = (uint32_t)row * 128 + (uint32_t)((seg ^ (row & 7)) << 4);
            *(uint4*)(ZoH + ((size_t)(b * N_ + m0 + row)) * C_ + seg * 8) = *(const uint4*)(smem + O_ZH + so);
            *(uint4*)(ZoL + ((size_t)(b * N_ + m0 + row)) * C_ + seg * 8) = *(const uint4*)(smem + O_ZL + so);
        }
    }

    // theta epilogue on tensor cores: o = zn@theta[PASS] (+ x@theta0 for PASS 1)
    float o[4][4] = {};
    mma_block64(sb + O_ZH, sb + O_ZL, sb + O_TH, sb + O_TL, wm, wn, lane, o);
    if (PASS == 1)
        mma_block64(sb + O_XH, sb + O_XL, sb + O_T0H, sb + O_T0L, wm, wn, lane, o);

    float* ob = out + ((size_t)(b * N_ + m0)) * C_;
    #pragma unroll
    for (int j = 0; j < 4; j++) {
        float2 v0 = make_float2(o[j][0], o[j][1]);
        float2 v1 = make_float2(o[j][2], o[j][3]);
        float* p0 = ob + (size_t)crow * C_ + ccol + j * 8;
        float* p1 = ob + (size_t)(crow + 8) * C_ + ccol + j * 8;
        if (PASS > 1) {
            float2 c0 = *(const float2*)p0, c1 = *(const float2*)p1;
            v0.x += c0.x; v0.y += c0.y; v1.x += c1.x; v1.y += c1.y;
        }
        *(float2*)p0 = v0;
        *(float2*)p1 = v1;
    }
}

extern "C" void kernel_launch(void* const* d_in, const int* in_sizes, int n_in,
                              void* d_out, int out_size) {
    (void)in_sizes; (void)n_in; (void)out_size;
    const float* x  = (const float*)d_in[0];   // [8,1024,64]
    const float* L  = (const float*)d_in[1];   // [8,1024,1024]
    const float* th = (const float*)d_in[2];   // [4,64,64]
    float* out = (float*)d_out;                // [8,1024,64]

    __nv_bfloat16 *lh, *ll, *xh, *xl, *z1h, *z1l, *z2h, *z2l, *thh, *thl;
    float* z1f;
    cudaGetSymbolAddress((void**)&lh, g_LH);
    cudaGetSymbolAddress((void**)&ll, g_LL);
    cudaGetSymbolAddress((void**)&xh, g_xH);
    cudaGetSymbolAddress((void**)&xl, g_xL);
    cudaGetSymbolAddress((void**)&z1h, g_z1H);
    cudaGetSymbolAddress((void**)&z1l, g_z1L);
    cudaGetSymbolAddress((void**)&z2h, g_z2H);
    cudaGetSymbolAddress((void**)&z2l, g_z2L);
    cudaGetSymbolAddress((void**)&thh, g_thH);
    cudaGetSymbolAddress((void**)&thl, g_thL);
    cudaGetSymbolAddress((void**)&z1f, g_Z1f);

    static bool attr_done = false;
    if (!attr_done) {
        cudaFuncSetAttribute(cheb<1>, cudaFuncAttributeMaxDynamicSharedMemorySize, SMEMSZ);
        cudaFuncSetAttribute(cheb<2>, cudaFuncAttributeMaxDynamicSharedMemorySize, SMEMSZ);
        cudaFuncSetAttribute(cheb<3>, cudaFuncAttributeMaxDynamicSharedMemorySize, SMEMSZ);
        attr_done = true;
    }

    // one prep launch: L, x, theta hi/lo splits
    split_all<<<2177, 256>>>((const float4*)L, (uint2*)lh, (uint2*)ll,
                             (const float4*)x, (uint2*)xh, (uint2*)xl,
                             (const float4*)th, (uint2*)thh, (uint2*)thl);

    dim3 grid(16, 8);
    // pass1: z1 = L x ; out  = x@th0 + z1@th1 ; side: z1f, z1 hi/lo
    cheb<1><<<grid, 256, SMEMSZ>>>(lh, ll, xh, xl, nullptr, thh, thl, xh, xl,
                                   z1f, z1h, z1l, out);
    // pass2: z2 = 2 L z1 - x ; out += z2@th2 ; side: z2 hi/lo
    cheb<2><<<grid, 256, SMEMSZ>>>(lh, ll, z1h, z1l, x, thh, thl, xh, xl,
                                   nullptr, z2h, z2l, out);
    // pass3: z3 = 2 L z2 - z1 ; out += z3@th3
    cheb<3><<<grid, 256, SMEMSZ>>>(lh, ll, z2h, z2l, z1f, thh, thl, xh, xl,
                                   nullptr, z1h, z1l, out);
}

// round 15
// speedup vs baseline: 1.1988x; 1.1034x over previous
#include <cuda_runtime.h>
#include <cuda_bf16.h>
#include <cstdint>

#define B_ 8
#define N_ 1024
#define C_ 64

// ---------------- device scratch (allocation-free rule) ----------------
__device__ __nv_bfloat16 g_LH[B_ * N_ * N_];
__device__ __nv_bfloat16 g_LL[B_ * N_ * N_];
__device__ __nv_bfloat16 g_xH[B_ * N_ * C_];
__device__ __nv_bfloat16 g_xL[B_ * N_ * C_];
__device__ __nv_bfloat16 g_z1H[B_ * N_ * C_];
__device__ __nv_bfloat16 g_z1L[B_ * N_ * C_];
__device__ __nv_bfloat16 g_z2H[B_ * N_ * C_];
__device__ __nv_bfloat16 g_z2L[B_ * N_ * C_];
__device__ float         g_Z1f[B_ * N_ * C_];
__device__ __nv_bfloat16 g_thH[4 * 64 * 64];   // theta[k][ci][co] bf16-hi
__device__ __nv_bfloat16 g_thL[4 * 64 * 64];   // bf16-lo

// ---------------- helpers ----------------
__device__ __forceinline__ uint32_t smem_u32(const void* p) {
    uint32_t a;
    asm("{ .reg .u64 t; cvta.to.shared.u64 t, %1; cvt.u32.u64 %0, t; }" : "=r"(a) : "l"(p));
    return a;
}
__device__ __forceinline__ void cp16(uint32_t d, const void* s) {
    asm volatile("cp.async.cg.shared.global [%0], [%1], 16;" :: "r"(d), "l"(s));
}
#define CP_COMMIT() asm volatile("cp.async.commit_group;" ::: "memory")

__device__ __forceinline__ void split2(float a, float b, uint32_t& hi, uint32_t& lo) {
    __nv_bfloat16 ha = __float2bfloat16(a), hb = __float2bfloat16(b);
    hi = (uint32_t)__bfloat16_as_ushort(ha) | ((uint32_t)__bfloat16_as_ushort(hb) << 16);
    __nv_bfloat16 la = __float2bfloat16(a - __bfloat162float(ha));
    __nv_bfloat16 lb = __float2bfloat16(b - __bfloat162float(hb));
    lo = (uint32_t)__bfloat16_as_ushort(la) | ((uint32_t)__bfloat16_as_ushort(lb) << 16);
}

#define LDSM4(R, A) asm volatile( \
    "ldmatrix.sync.aligned.m8n8.x4.shared.b16 {%0,%1,%2,%3}, [%4];" \
    : "=r"((R)[0]), "=r"((R)[1]), "=r"((R)[2]), "=r"((R)[3]) : "r"(A))
#define LDSM4T(R, A) asm volatile( \
    "ldmatrix.sync.aligned.m8n8.x4.trans.shared.b16 {%0,%1,%2,%3}, [%4];" \
    : "=r"((R)[0]), "=r"((R)[1]), "=r"((R)[2]), "=r"((R)[3]) : "r"(A))
#define MMA16816(D, A, B0, B1) asm volatile( \
    "mma.sync.aligned.m16n8k16.row.col.f32.bf16.bf16.f32 " \
    "{%0,%1,%2,%3},{%4,%5,%6,%7},{%8,%9},{%0,%1,%2,%3};" \
    : "+f"((D)[0]), "+f"((D)[1]), "+f"((D)[2]), "+f"((D)[3]) \
    : "r"((A)[0]), "r"((A)[1]), "r"((A)[2]), "r"((A)[3]), "r"(B0), "r"(B1))

// 16m x 32n per warp, K=64 sub-chunk, bf16-split (HH + HL + LH). R4-proven,
// byte-identical logic to the 56.3us version.
__device__ __forceinline__ void mma_block64(
    uint32_t aH, uint32_t aL, uint32_t bH, uint32_t bL,
    int wm, int wn, int lane, float acc[4][4]) {
    const int tile = lane >> 3, tl = lane & 7;
    const int arow = wm * 16 + ((tile & 1) << 3) + tl;
    const uint32_t arb = (uint32_t)arow * 128;
    const int arx = arow & 7;
    const int aks0 = tile >> 1;
    const int krl = ((tile & 1) << 3) + tl;
    const int bs0 = wn * 4 + (tile >> 1);
    #pragma unroll
    for (int kk = 0; kk < 4; kk++) {
        uint32_t aso = arb + (uint32_t)(((aks0 + kk * 2) ^ arx) << 4);
        uint32_t AH4[4], AL4[4];
        LDSM4(AH4, aH + aso);
        LDSM4(AL4, aL + aso);
        const int kr = kk * 16 + krl;
        const int krx = kr & 7;
        const uint32_t krb = (uint32_t)kr * 128;
        uint32_t bso0 = krb + (uint32_t)(((bs0 + 0) ^ krx) << 4);
        uint32_t bso1 = krb + (uint32_t)(((bs0 + 2) ^ krx) << 4);
        uint32_t BH0[4], BH1[4], BL0[4], BL1[4];
        LDSM4T(BH0, bH + bso0);
        LDSM4T(BH1, bH + bso1);
        LDSM4T(BL0, bL + bso0);
        LDSM4T(BL1, bL + bso1);
        MMA16816(acc[0], AH4, BH0[0], BH0[1]);
        MMA16816(acc[1], AH4, BH0[2], BH0[3]);
        MMA16816(acc[2], AH4, BH1[0], BH1[1]);
        MMA16816(acc[3], AH4, BH1[2], BH1[3]);
        MMA16816(acc[0], AH4, BL0[0], BL0[1]);
        MMA16816(acc[1], AH4, BL0[2], BL0[3]);
        MMA16816(acc[2], AH4, BL1[0], BL1[1]);
        MMA16816(acc[3], AH4, BL1[2], BL1[3]);
        MMA16816(acc[0], AL4, BH0[0], BH0[1]);
        MMA16816(acc[1], AL4, BH0[2], BH0[3]);
        MMA16816(acc[2], AL4, BH1[0], BH1[1]);
        MMA16816(acc[3], AL4, BH1[2], BH1[3]);
    }
}

// ---------------- prep: fp32 -> bf16 hi/lo split for L, x, theta in ONE launch ----------------
__global__ __launch_bounds__(256) void split_all(
    const float4* __restrict__ L4, uint2* __restrict__ lh, uint2* __restrict__ ll,
    const float4* __restrict__ x4, uint2* __restrict__ xh, uint2* __restrict__ xl,
    const float4* __restrict__ t4, uint2* __restrict__ th, uint2* __restrict__ tl) {
    if (blockIdx.x < 2048) {
        const int n4 = B_ * N_ * N_ / 4;
        const int stride = 2048 * 256;
        for (int i = blockIdx.x * 256 + threadIdx.x; i < n4; i += stride) {
            float4 v = L4[i];
            uint32_t h0, l0, h1, l1;
            split2(v.x, v.y, h0, l0);
            split2(v.z, v.w, h1, l1);
            lh[i] = make_uint2(h0, h1);
            ll[i] = make_uint2(l0, l1);
        }
    } else if (blockIdx.x < 2176) {
        const int n4 = B_ * N_ * C_ / 4;
        const int stride = 128 * 256;
        for (int i = (blockIdx.x - 2048) * 256 + threadIdx.x; i < n4; i += stride) {
            float4 v = x4[i];
            uint32_t h0, l0, h1, l1;
            split2(v.x, v.y, h0, l0);
            split2(v.z, v.w, h1, l1);
            xh[i] = make_uint2(h0, h1);
            xl[i] = make_uint2(l0, l1);
        }
    } else {
        const int n4 = 4 * 64 * 64 / 4;
        for (int i = threadIdx.x; i < n4; i += 256) {
            float4 v = t4[i];
            uint32_t h0, l0, h1, l1;
            split2(v.x, v.y, h0, l0);
            split2(v.z, v.w, h1, l1);
            th[i] = make_uint2(h0, h1);
            tl[i] = make_uint2(l0, l1);
        }
    }
}

// ---------------- main pass kernel (R4 mainloop, K-chunk=128, 2 stages) ----------------
// M-tile = 64 rows, 256 threads (8 warps: wm{0..3} x wn{0,1}), full K per warp.
// stage (64KB) = two 32KB sub-stages, each R4 layout:
//   sub: A_hi [0,8K) A_lo [8K,16K) B_hi [16K,24K) B_lo [24K,32K)
// Loop: 8 chunks of K=128, ONE wait/commit/sync per chunk, MMA-first ordering.
// Epilogue aliases stage 0 (dead after mainloop).
#define SUB    32768
#define STG    65536
#define O_ZH   0
#define O_ZL   8192
#define O_TH   16384
#define O_TL   24576
#define O_XH   32768
#define O_XL   40960
#define O_T0H  49152
#define O_T0L  57344
#define SMEMSZ (2 * STG)   // 131072

template <int PASS>
__global__ void __launch_bounds__(256, 1) cheb(
    const __nv_bfloat16* __restrict__ LH, const __nv_bfloat16* __restrict__ LL,
    const __nv_bfloat16* __restrict__ BHg, const __nv_bfloat16* __restrict__ BLg,
    const float* __restrict__ Sub,
    const __nv_bfloat16* __restrict__ thH, const __nv_bfloat16* __restrict__ thL,
    const __nv_bfloat16* __restrict__ xH, const __nv_bfloat16* __restrict__ xL,
    float* __restrict__ Zf,
    __nv_bfloat16* __restrict__ ZoH, __nv_bfloat16* __restrict__ ZoL,
    float* __restrict__ out) {

    extern __shared__ char smem[];
    const uint32_t sb = smem_u32(smem);
    const int tid = threadIdx.x, lane = tid & 31, wid = tid >> 5;
    const int wm = wid & 3, wn = wid >> 2;
    const int b = blockIdx.y, m0 = blockIdx.x * 64;

    const __nv_bfloat16* ApH = LH + ((size_t)(b * N_ + m0)) * N_;
    const __nv_bfloat16* ApL = LL + ((size_t)(b * N_ + m0)) * N_;
    const __nv_bfloat16* BpH = BHg + (size_t)b * N_ * C_;
    const __nv_bfloat16* BpL = BLg + (size_t)b * N_ * C_;

    // one chunk = 128 k-columns = two R4-style 32KB sub-stages; single commit
    auto load_chunk = [&](int k0, uint32_t st) {
        #pragma unroll
        for (int half = 0; half < 2; half++) {
            const uint32_t ss = st + (uint32_t)half * SUB;
            const int kh = k0 + half * 64;
            #pragma unroll
            for (int i = 0; i < 2; i++) {
                const int idx = tid + i * 256;
                const int row = idx >> 3, seg = idx & 7;
                const uint32_t so = (uint32_t)row * 128 + (uint32_t)((seg ^ (row & 7)) << 4);
                cp16(ss + so,         ApH + (size_t)row * N_ + kh + seg * 8);
                cp16(ss + 8192 + so,  ApL + (size_t)row * N_ + kh + seg * 8);
                cp16(ss + 16384 + so, BpH + (size_t)(kh + row) * C_ + seg * 8);
                cp16(ss + 24576 + so, BpL + (size_t)(kh + row) * C_ + seg * 8);
            }
        }
        CP_COMMIT();
    };

    float acc[4][4] = {};
    load_chunk(0, sb);
    load_chunk(128, sb + STG);

    for (int ch = 0; ch < 8; ch++) {
        if (ch < 7) asm volatile("cp.async.wait_group 1;" ::: "memory");
        else        asm volatile("cp.async.wait_group 0;" ::: "memory");
        __syncthreads();
        const uint32_t st = sb + (uint32_t)(ch & 1) * STG;
        mma_block64(st, st + 8192, st + 16384, st + 24576, wm, wn, lane, acc);
        mma_block64(st + SUB, st + SUB + 8192, st + SUB + 16384, st + SUB + 24576,
                    wm, wn, lane, acc);
        if (ch + 2 < 8) load_chunk((ch + 2) * 128, st);   // reuse current stage slot
    }
    __syncthreads();   // stage 0 dead -> epilogue aliases it

    // ---- zn = alpha*acc - Sub ----
    const int crow = wm * 16 + (lane >> 2);
    const int ccol = wn * 32 + 2 * (lane & 3);
    float zn[4][4];
    if (PASS == 1) {
        #pragma unroll
        for (int j = 0; j < 4; j++)
            #pragma unroll
            for (int q = 0; q < 4; q++) zn[j][q] = acc[j][q];
    } else {
        const float* Sb = Sub + ((size_t)(b * N_ + m0)) * C_;
        #pragma unroll
        for (int j = 0; j < 4; j++) {
            float2 s0 = *(const float2*)(Sb + (size_t)crow * C_ + ccol + j * 8);
            float2 s1 = *(const float2*)(Sb + (size_t)(crow + 8) * C_ + ccol + j * 8);
            zn[j][0] = 2.f * acc[j][0] - s0.x;
            zn[j][1] = 2.f * acc[j][1] - s0.y;
            zn[j][2] = 2.f * acc[j][2] - s1.x;
            zn[j][3] = 2.f * acc[j][3] - s1.y;
        }
    }

    // zn -> smem (bf16 hi/lo, SW128 rows)
    #pragma unroll
    for (int j = 0; j < 4; j++) {
        const int seg = wn * 4 + j;
        const int off = (lane & 3) * 4;
        #pragma unroll
        for (int h = 0; h < 2; h++) {
            const int row = crow + h * 8;
            uint32_t hi, lo;
            split2(zn[j][2 * h], zn[j][2 * h + 1], hi, lo);
            const uint32_t so = (uint32_t)row * 128 + (uint32_t)((seg ^ (row & 7)) << 4) + off;
            *(uint32_t*)(smem + O_ZH + so) = hi;
            *(uint32_t*)(smem + O_ZL + so) = lo;
        }
    }
    if (PASS == 1) {  // z1 fp32 for pass3's Sub
        float* Zb = Zf + ((size_t)(b * N_ + m0)) * C_;
        #pragma unroll
        for (int j = 0; j < 4; j++) {
            *(float2*)(Zb + (size_t)crow * C_ + ccol + j * 8)       = make_float2(zn[j][0], zn[j][1]);
            *(float2*)(Zb + (size_t)(crow + 8) * C_ + ccol + j * 8) = make_float2(zn[j][2], zn[j][3]);
        }
    }

    // stage theta (and x, theta0 for pass 1)
    const __nv_bfloat16* tHk = thH + PASS * 4096;
    const __nv_bfloat16* tLk = thL + PASS * 4096;
    #pragma unroll
    for (int i = 0; i < 2; i++) {
        const int idx = tid + i * 256;
        const int row = idx >> 3, seg = idx & 7;
        const uint32_t so = (uint32_t)row * 128 + (uint32_t)((seg ^ (row & 7)) << 4);
        *(uint4*)(smem + O_TH + so) = *(const uint4*)(tHk + row * 64 + seg * 8);
        *(uint4*)(smem + O_TL + so) = *(const uint4*)(tLk + row * 64 + seg * 8);
        if (PASS == 1) {
            *(uint4*)(smem + O_XH + so) = *(const uint4*)(xH + ((size_t)(b * N_ + m0 + row)) * C_ + seg * 8);
            *(uint4*)(smem + O_XL + so) = *(const uint4*)(xL + ((size_t)(b * N_ + m0 + row)) * C_ + seg * 8);
            *(uint4*)(smem + O_T0H + so) = *(const uint4*)(thH + row * 64 + seg * 8);
            *(uint4*)(smem + O_T0L + so) = *(const uint4*)(thL + row * 64 + seg * 8);
        }
    }
    __syncthreads();

    // zn (hi/lo) -> global row-major [N][C]: next pass's B operand
    if (PASS < 3) {
        #pragma unroll
        for (int i = 0; i < 2; i++) {
            const int idx = tid + i * 256;
            const int row = idx >> 3, seg = idx & 7;
            const uint32_t so = (uint32_t)row * 128 + (uint32_t)((seg ^ (row & 7)) << 4);
            *(uint4*)(ZoH + ((size_t)(b * N_ + m0 + row)) * C_ + seg * 8) = *(const uint4*)(smem + O_ZH + so);
            *(uint4*)(ZoL + ((size_t)(b * N_ + m0 + row)) * C_ + seg * 8) = *(const uint4*)(smem + O_ZL + so);
        }
    }

    // theta epilogue on tensor cores: o = zn@theta[PASS] (+ x@theta0 for PASS 1)
    float o[4][4] = {};
    mma_block64(sb + O_ZH, sb + O_ZL, sb + O_TH, sb + O_TL, wm, wn, lane, o);
    if (PASS == 1)
        mma_block64(sb + O_XH, sb + O_XL, sb + O_T0H, sb + O_T0L, wm, wn, lane, o);

    float* ob = out + ((size_t)(b * N_ + m0)) * C_;
    #pragma unroll
    for (int j = 0; j < 4; j++) {
        float2 v0 = make_float2(o[j][0], o[j][1]);
        float2 v1 = make_float2(o[j][2], o[j][3]);
        float* p0 = ob + (size_t)crow * C_ + ccol + j * 8;
        float* p1 = ob + (size_t)(crow + 8) * C_ + ccol + j * 8;
        if (PASS > 1) {
            float2 c0 = *(const float2*)p0, c1 = *(const float2*)p1;
            v0.x += c0.x; v0.y += c0.y; v1.x += c1.x; v1.y += c1.y;
        }
        *(float2*)p0 = v0;
        *(float2*)p1 = v1;
    }
}

extern "C" void kernel_launch(void* const* d_in, const int* in_sizes, int n_in,
                              void* d_out, int out_size) {
    (void)in_sizes; (void)n_in; (void)out_size;
    const float* x  = (const float*)d_in[0];   // [8,1024,64]
    const float* L  = (const float*)d_in[1];   // [8,1024,1024]
    const float* th = (const float*)d_in[2];   // [4,64,64]
    float* out = (float*)d_out;                // [8,1024,64]

    __nv_bfloat16 *lh, *ll, *xh, *xl, *z1h, *z1l, *z2h, *z2l, *thh, *thl;
    float* z1f;
    cudaGetSymbolAddress((void**)&lh, g_LH);
    cudaGetSymbolAddress((void**)&ll, g_LL);
    cudaGetSymbolAddress((void**)&xh, g_xH);
    cudaGetSymbolAddress((void**)&xl, g_xL);
    cudaGetSymbolAddress((void**)&z1h, g_z1H);
    cudaGetSymbolAddress((void**)&z1l, g_z1L);
    cudaGetSymbolAddress((void**)&z2h, g_z2H);
    cudaGetSymbolAddress((void**)&z2l, g_z2L);
    cudaGetSymbolAddress((void**)&thh, g_thH);
    cudaGetSymbolAddress((void**)&thl, g_thL);
    cudaGetSymbolAddress((void**)&z1f, g_Z1f);

    static bool attr_done = false;
    if (!attr_done) {
        cudaFuncSetAttribute(cheb<1>, cudaFuncAttributeMaxDynamicSharedMemorySize, SMEMSZ);
        cudaFuncSetAttribute(cheb<2>, cudaFuncAttributeMaxDynamicSharedMemorySize, SMEMSZ);
        cudaFuncSetAttribute(cheb<3>, cudaFuncAttributeMaxDynamicSharedMemorySize, SMEMSZ);
        attr_done = true;
    }

    // one prep launch: L, x, theta hi/lo splits
    split_all<<<2177, 256>>>((const float4*)L, (uint2*)lh, (uint2*)ll,
                             (const float4*)x, (uint2*)xh, (uint2*)xl,
                             (const float4*)th, (uint2*)thh, (uint2*)thl);

    dim3 grid(16, 8);
    // pass1: z1 = L x ; out  = x@th0 + z1@th1 ; side: z1f, z1 hi/lo
    cheb<1><<<grid, 256, SMEMSZ>>>(lh, ll, xh, xl, nullptr, thh, thl, xh, xl,
                                   z1f, z1h, z1l, out);
    // pass2: z2 = 2 L z1 - x ; out += z2@th2 ; side: z2 hi/lo
    cheb<2><<<grid, 256, SMEMSZ>>>(lh, ll, z1h, z1l, x, thh, thl, xh, xl,
                                   nullptr, z2h, z2l, out);
    // pass3: z3 = 2 L z2 - z1 ; out += z3@th3
    cheb<3><<<grid, 256, SMEMSZ>>>(lh, ll, z2h, z2l, z1f, thh, thl, xh, xl,
                                   nullptr, z1h, z1l, out);
}